// round 6
// baseline (speedup 1.0000x reference)
#include <cuda_runtime.h>
#include <cuda_bf16.h>
#include <cstdint>

#define NQ 12288
#define SPLIT 3
#define KPB (NQ / SPLIT)   // 4096
#define KT 64
#define NT (KPB / KT)      // 64 tiles per CTA
#define QT 128
#define VROW 144           // padded SMEM row stride for V^T (bytes)
#define VSP 72             // vS padded stride (uint16)

// ---- scratch (no cudaMalloc allowed) ----
__device__ __align__(16) unsigned char g_Qhi[NQ * 16];            // 8 bf16 (scaled q, hi)
__device__ __align__(16) unsigned char g_Qlo[NQ * 16];            // 8 bf16 (residual)
__device__ __align__(16) unsigned char g_Kd[NQ * 16];             // 8 bf16 per key
__device__ __align__(16) unsigned char g_Vt[(NQ / 64) * 8192];    // [tile][c 0..63][key 0..63] bf16
__device__ __align__(16) float g_num[SPLIT * NQ * 64];
__device__ __align__(16) float g_den[SPLIT * NQ];

// ============ helpers ============
__device__ __forceinline__ float ex2f(float x) {
    float r; asm("ex2.approx.ftz.f32 %0, %1;" : "=f"(r) : "f"(x)); return r;
}
__device__ __forceinline__ uint32_t pack_bf2(float lo, float hi) {
    uint32_t r;
    asm("cvt.rn.bf16x2.f32 %0, %1, %2;" : "=r"(r) : "f"(hi), "f"(lo));
    return r;
}
__device__ __forceinline__ void cp16(uint32_t dst, const void* src) {
    asm volatile("cp.async.ca.shared.global [%0], [%1], 16;" :: "r"(dst), "l"(src) : "memory");
}
#define CP_COMMIT() asm volatile("cp.async.commit_group;" ::: "memory")
#define CP_WAIT0()  asm volatile("cp.async.wait_group 0;" ::: "memory")

__device__ __forceinline__ uint32_t smem_u32(const void* p) {
    uint32_t a;
    asm("{ .reg .u64 t; cvta.to.shared.u64 t, %1; cvt.u32.u64 %0, t; }" : "=r"(a) : "l"(p));
    return a;
}
__device__ __forceinline__ void mma_bf16(float d[4], uint32_t a0, uint32_t a1, uint32_t a2,
                                         uint32_t a3, uint32_t b0, uint32_t b1) {
    asm volatile("mma.sync.aligned.m16n8k16.row.col.f32.bf16.bf16.f32 "
                 "{%0,%1,%2,%3}, {%4,%5,%6,%7}, {%8,%9}, {%0,%1,%2,%3};"
                 : "+f"(d[0]), "+f"(d[1]), "+f"(d[2]), "+f"(d[3])
                 : "r"(a0), "r"(a1), "r"(a2), "r"(a3), "r"(b0), "r"(b1));
}

__device__ __forceinline__ void acc16(float h[16], float x, const float4* wrow) {
    float4 a = wrow[0], b = wrow[1], c = wrow[2], d = wrow[3];
    h[0] = fmaf(x, a.x, h[0]);  h[1] = fmaf(x, a.y, h[1]);
    h[2] = fmaf(x, a.z, h[2]);  h[3] = fmaf(x, a.w, h[3]);
    h[4] = fmaf(x, b.x, h[4]);  h[5] = fmaf(x, b.y, h[5]);
    h[6] = fmaf(x, b.z, h[6]);  h[7] = fmaf(x, b.w, h[7]);
    h[8] = fmaf(x, c.x, h[8]);  h[9] = fmaf(x, c.y, h[9]);
    h[10] = fmaf(x, c.z, h[10]); h[11] = fmaf(x, c.w, h[11]);
    h[12] = fmaf(x, d.x, h[12]); h[13] = fmaf(x, d.y, h[13]);
    h[14] = fmaf(x, d.z, h[14]); h[15] = fmaf(x, d.w, h[15]);
}

// ---------------------------------------------------------------------------
// Kernel A: 4 threads per row. CTA = 64 rows (= one V tile), 256 threads.
// ---------------------------------------------------------------------------
__global__ __launch_bounds__(256) void qkv_kernel(
    const float* __restrict__ xm, const float* __restrict__ xd,
    const float* __restrict__ W1, const float* __restrict__ W2,
    const float* __restrict__ Wq, const float* __restrict__ Wk,
    const float* __restrict__ Wv) {
    __shared__ __align__(16) float4 W1s[192 * 4];
    __shared__ __align__(16) float4 W2s[16 * 4];
    __shared__ float Wqs[16 * 8];
    __shared__ float Wks[16 * 8];
    __shared__ __align__(16) float4 Wvs[16 * 16];
    __shared__ uint16_t vS[64 * VSP];

    const int tid = threadIdx.x;
    const int tp = tid & 3;           // sub-row worker 0..3
    const int rl = tid >> 2;          // local row 0..63
    const int r = blockIdx.x * 64 + rl;

    for (int i = tid; i < 192 * 4; i += 256) W1s[i] = ((const float4*)W1)[i];
    for (int i = tid; i < 16 * 4; i += 256) W2s[i] = ((const float4*)W2)[i];
    if (tid < 128) { Wqs[tid] = Wq[tid]; Wks[tid] = Wk[tid]; }
    for (int i = tid; i < 16 * 16; i += 256) Wvs[i] = ((const float4*)Wv)[i];
    __syncthreads();

    // ---- h1 partial over 48 of 192 input dims (f = 4i + tp) ----
    float h1[16];
#pragma unroll
    for (int j = 0; j < 16; j++) h1[j] = 0.f;
    const float4* xm4 = (const float4*)(xm + (size_t)r * 64);
    const float4* xd4 = (const float4*)(xd + (size_t)r * 128);
#pragma unroll
    for (int i = 0; i < 12; i++) {
        int f = 4 * i + tp;                       // global float4 index 0..47
        float4 xv = (i < 4) ? xm4[f] : xd4[f - 16];
        int d = 4 * f;
        acc16(h1, xv.x, &W1s[(d + 0) * 4]);
        acc16(h1, xv.y, &W1s[(d + 1) * 4]);
        acc16(h1, xv.z, &W1s[(d + 2) * 4]);
        acc16(h1, xv.w, &W1s[(d + 3) * 4]);
    }
    // quad-reduce (lanes of a quad share the row)
#pragma unroll
    for (int j = 0; j < 16; j++) {
        h1[j] += __shfl_xor_sync(0xffffffffu, h1[j], 1);
        h1[j] += __shfl_xor_sync(0xffffffffu, h1[j], 2);
        h1[j] = fmaxf(h1[j], 0.f);
    }

    // ---- h2: 4 outputs per thread, then all-gather ----
    float h2p[4] = {0.f, 0.f, 0.f, 0.f};
#pragma unroll
    for (int k = 0; k < 16; k++) {
        float4 w = W2s[k * 4 + tp];
        float hk = h1[k];
        h2p[0] = fmaf(hk, w.x, h2p[0]);
        h2p[1] = fmaf(hk, w.y, h2p[1]);
        h2p[2] = fmaf(hk, w.z, h2p[2]);
        h2p[3] = fmaf(hk, w.w, h2p[3]);
    }
#pragma unroll
    for (int c = 0; c < 4; c++) h2p[c] = fmaxf(h2p[c], 0.f);

    float h2[16];
    {
        const int lane = tid & 31;
        const int base = lane & ~3;
#pragma unroll
        for (int j = 0; j < 16; j++)
            h2[j] = __shfl_sync(0xffffffffu, h2p[j & 3], base | (j >> 2));
    }

    // ---- Q/K: outputs j = 2tp, 2tp+1 ----
    {
        float q0 = 0.f, q1 = 0.f, k0 = 0.f, k1 = 0.f;
        const int j0 = 2 * tp;
#pragma unroll
        for (int k = 0; k < 16; k++) {
            float hk = h2[k];
            q0 = fmaf(hk, Wqs[k * 8 + j0], q0);
            q1 = fmaf(hk, Wqs[k * 8 + j0 + 1], q1);
            k0 = fmaf(hk, Wks[k * 8 + j0], k0);
            k1 = fmaf(hk, Wks[k * 8 + j0 + 1], k1);
        }
        const float QS = (float)(1.4426950408889634 / 2.8284271247461903);
        q0 *= QS; q1 *= QS;
        __nv_bfloat16 h0 = __float2bfloat16(q0);
        __nv_bfloat16 h1b = __float2bfloat16(q1);
        float r0 = q0 - __bfloat162float(h0);
        float r1 = q1 - __bfloat162float(h1b);
        __nv_bfloat16 l0 = __float2bfloat16(r0);
        __nv_bfloat16 l1 = __float2bfloat16(r1);
        __nv_bfloat16 kb0 = __float2bfloat16(k0);
        __nv_bfloat16 kb1 = __float2bfloat16(k1);
        uint32_t hi = (uint32_t)*(uint16_t*)&h0 | ((uint32_t)*(uint16_t*)&h1b << 16);
        uint32_t lo = (uint32_t)*(uint16_t*)&l0 | ((uint32_t)*(uint16_t*)&l1 << 16);
        uint32_t kk = (uint32_t)*(uint16_t*)&kb0 | ((uint32_t)*(uint16_t*)&kb1 << 16);
        *(uint32_t*)(g_Qhi + (size_t)r * 16 + 4 * tp) = hi;
        *(uint32_t*)(g_Qlo + (size_t)r * 16 + 4 * tp) = lo;
        *(uint32_t*)(g_Kd + (size_t)r * 16 + 4 * tp) = kk;
    }

    // ---- V: cols [16tp, 16tp+16) ----
    {
        float v[16];
#pragma unroll
        for (int c = 0; c < 16; c++) v[c] = 0.f;
#pragma unroll
        for (int k = 0; k < 16; k++) {
            float hk = h2[k];
            const float4* wr = &Wvs[k * 16 + tp * 4];
#pragma unroll
            for (int c4 = 0; c4 < 4; c4++) {
                float4 w = wr[c4];
                v[4 * c4 + 0] = fmaf(hk, w.x, v[4 * c4 + 0]);
                v[4 * c4 + 1] = fmaf(hk, w.y, v[4 * c4 + 1]);
                v[4 * c4 + 2] = fmaf(hk, w.z, v[4 * c4 + 2]);
                v[4 * c4 + 3] = fmaf(hk, w.w, v[4 * c4 + 3]);
            }
        }
        uint32_t* dst = (uint32_t*)&vS[rl * VSP + tp * 16];
#pragma unroll
        for (int p = 0; p < 8; p++) {
            __nv_bfloat16 b0 = __float2bfloat16(v[2 * p]);
            __nv_bfloat16 b1 = __float2bfloat16(v[2 * p + 1]);
            dst[p] = (uint32_t)*(uint16_t*)&b0 | ((uint32_t)*(uint16_t*)&b1 << 16);
        }
    }
    __syncthreads();

    // ---- transpose write: thread (c = tid>>2, part = tid&3) ----
    {
        int c = tid >> 2, part = tid & 3;
        uint16_t tmp[16];
#pragma unroll
        for (int u = 0; u < 16; u++)
            tmp[u] = vS[(part * 16 + u) * VSP + c];
        unsigned char* dst = g_Vt + (size_t)blockIdx.x * 8192 + (size_t)c * 128 + part * 32;
        *(uint4*)dst = *(uint4*)tmp;
        *(uint4*)(dst + 16) = *(uint4*)(tmp + 8);
    }
}

// ---------------------------------------------------------------------------
// Kernel B: mma.sync bf16 flash attention. CTA = 128 queries, 8 warps.
// ---------------------------------------------------------------------------
__device__ __forceinline__ void prefetch_tile(uint32_t sKb, uint32_t sVb, int tid,
                                              const unsigned char* kptr,
                                              const unsigned char* vptr) {
    if (tid < 64) cp16(sKb + tid * 16, kptr + tid * 16);
    int r0 = tid >> 3, s0 = tid & 7;
    cp16(sVb + r0 * VROW + s0 * 16, vptr + r0 * 128 + s0 * 16);
    int i1 = tid + 256;
    int r1 = i1 >> 3, s1 = i1 & 7;
    cp16(sVb + r1 * VROW + s1 * 16, vptr + r1 * 128 + s1 * 16);
    CP_COMMIT();
}

__global__ __launch_bounds__(256, 2) void attn_kernel() {
    __shared__ __align__(16) unsigned char sK[2][1024];
    __shared__ __align__(16) unsigned char sV[2][64 * VROW];

    const int tid = threadIdx.x;
    const int wid = tid >> 5, lane = tid & 31;
    const int gr = lane >> 2, tig = lane & 3;
    const int qbase = blockIdx.x * QT;
    const int kbase = blockIdx.y * KPB;
    const int tile0 = kbase >> 6;
    const int m0 = qbase + wid * 16 + gr;

    const uint32_t qa0 = *(const uint32_t*)(g_Qhi + (size_t)m0 * 16 + 4 * tig);
    const uint32_t qa1 = *(const uint32_t*)(g_Qhi + (size_t)(m0 + 8) * 16 + 4 * tig);
    const uint32_t qa2 = *(const uint32_t*)(g_Qlo + (size_t)m0 * 16 + 4 * tig);
    const uint32_t qa3 = *(const uint32_t*)(g_Qlo + (size_t)(m0 + 8) * 16 + 4 * tig);

    float o[8][4];
#pragma unroll
    for (int i = 0; i < 8; i++)
#pragma unroll
        for (int j = 0; j < 4; j++) o[i][j] = 0.f;
    float den0 = 0.f, den1 = 0.f;

    const uint32_t sKb0 = smem_u32(sK[0]), sKb1 = smem_u32(sK[1]);
    const uint32_t sVb0 = smem_u32(sV[0]), sVb1 = smem_u32(sV[1]);

    prefetch_tile(sKb0, sVb0, tid, g_Kd + (size_t)kbase * 16, g_Vt + (size_t)tile0 * 8192);

    for (int t = 0; t < NT; t++) {
        CP_WAIT0();
        __syncthreads();
        if (t + 1 < NT) {
            int st = (t + 1) & 1;
            prefetch_tile(st ? sKb1 : sKb0, st ? sVb1 : sVb0, tid,
                          g_Kd + (size_t)(kbase + (t + 1) * 64) * 16,
                          g_Vt + (size_t)(tile0 + t + 1) * 8192);
        }
        const unsigned char* Ks = sK[t & 1];
        const unsigned char* Vs = sV[t & 1];

#pragma unroll
        for (int kc = 0; kc < 4; kc++) {
            float s0[4] = {0.f, 0.f, 0.f, 0.f};
            float s1[4] = {0.f, 0.f, 0.f, 0.f};
            uint32_t kb0 = *(const uint32_t*)(Ks + (16 * kc + gr) * 16 + 4 * tig);
            uint32_t kb1 = *(const uint32_t*)(Ks + (16 * kc + 8 + gr) * 16 + 4 * tig);
            mma_bf16(s0, qa0, qa1, qa2, qa3, kb0, kb0);
            mma_bf16(s1, qa0, qa1, qa2, qa3, kb1, kb1);

            float e00 = ex2f(s0[0]), e01 = ex2f(s0[1]), e02 = ex2f(s0[2]), e03 = ex2f(s0[3]);
            float e10 = ex2f(s1[0]), e11 = ex2f(s1[1]), e12 = ex2f(s1[2]), e13 = ex2f(s1[3]);
            den0 += (e00 + e01) + (e10 + e11);
            den1 += (e02 + e03) + (e12 + e13);
            uint32_t pa0 = pack_bf2(e00, e01);
            uint32_t pa1 = pack_bf2(e02, e03);
            uint32_t pa2 = pack_bf2(e10, e11);
            uint32_t pa3 = pack_bf2(e12, e13);

            const unsigned char* vb = Vs + gr * VROW + 32 * kc + 4 * tig;
#pragma unroll
            for (int nb = 0; nb < 8; nb++) {
                uint32_t vb0 = *(const uint32_t*)(vb + nb * 8 * VROW);
                uint32_t vb1 = *(const uint32_t*)(vb + nb * 8 * VROW + 16);
                mma_bf16(o[nb], pa0, pa1, pa2, pa3, vb0, vb1);
            }
        }
        __syncthreads();
    }

    den0 += __shfl_xor_sync(0xffffffffu, den0, 1);
    den0 += __shfl_xor_sync(0xffffffffu, den0, 2);
    den1 += __shfl_xor_sync(0xffffffffu, den1, 1);
    den1 += __shfl_xor_sync(0xffffffffu, den1, 2);
    if (tig == 0) {
        g_den[blockIdx.y * NQ + m0] = den0;
        g_den[blockIdx.y * NQ + m0 + 8] = den1;
    }

    float* np0 = g_num + ((size_t)blockIdx.y * NQ + m0) * 64;
    float* np1 = np0 + 8 * 64;
#pragma unroll
    for (int nb = 0; nb < 8; nb++) {
        *(float2*)(np0 + 8 * nb + 2 * tig) = make_float2(o[nb][0], o[nb][1]);
        *(float2*)(np1 + 8 * nb + 2 * tig) = make_float2(o[nb][2], o[nb][3]);
    }
}

// ---------------------------------------------------------------------------
// Kernel C: combine splits + divide
// ---------------------------------------------------------------------------
__global__ void combine_kernel(float* __restrict__ out) {
    int i = blockIdx.x * blockDim.x + threadIdx.x;
    if (i >= NQ * 64) return;
    int r = i >> 6;
    float s = 0.f, d = 0.f;
#pragma unroll
    for (int p = 0; p < SPLIT; p++) {
        s += g_num[(size_t)p * NQ * 64 + i];
        d += g_den[p * NQ + r];
    }
    out[i] = s / d;
}

extern "C" void kernel_launch(void* const* d_in, const int* in_sizes, int n_in,
                              void* d_out, int out_size) {
    const float* xm = (const float*)d_in[0];
    const float* xd = (const float*)d_in[1];
    const float* W1 = (const float*)d_in[3];
    const float* W2 = (const float*)d_in[4];
    const float* Wq = (const float*)d_in[5];
    const float* Wk = (const float*)d_in[6];
    const float* Wv = (const float*)d_in[7];

    qkv_kernel<<<NQ / 64, 256>>>(xm, xd, W1, W2, Wq, Wk, Wv);
    attn_kernel<<<dim3(NQ / QT, SPLIT), 256>>>();
    combine_kernel<<<(NQ * 64 + 255) / 256, 256>>>((float*)d_out);
}